// round 2
// baseline (speedup 1.0000x reference)
#include <cuda_runtime.h>
#include <cuda_bf16.h>

// UltraTinyGRU, two-phase:
//   Phase 1 (gru_xproj): x[B,T,16] @ w_ih^T + biases -> g_xp[B,T,4] float4(r,z,n,0)
//       (b_hh folded into r/z components; n keeps only b_ih, b_hh_n applied in scan)
//   Phase 2 (gru_scan): 4 threads per batch row run the 512-step recurrence,
//       reading one float4 per thread per step from g_xp.

#define GB 4096
#define GT 512
#define GF 16

// 134 MB static scratch: [B][T][j=0..3] float4
__device__ float4 g_xp[(size_t)GB * GT * 4];

__device__ __forceinline__ float fast_sigmoid(float x) {
    float e = __expf(-x);
    return __fdividef(1.0f, 1.0f + e);
}

__device__ __forceinline__ float fast_tanh(float x) {
    float e = __expf(-2.0f * x);
    return __fdividef(1.0f - e, 1.0f + e);
}

__device__ __forceinline__ float dot16(float4 c0, float4 c1, float4 c2, float4 c3,
                                       float4 w0, float4 w1, float4 w2, float4 w3,
                                       float acc) {
    acc = fmaf(c0.x, w0.x, acc); acc = fmaf(c0.y, w0.y, acc);
    acc = fmaf(c0.z, w0.z, acc); acc = fmaf(c0.w, w0.w, acc);
    acc = fmaf(c1.x, w1.x, acc); acc = fmaf(c1.y, w1.y, acc);
    acc = fmaf(c1.z, w1.z, acc); acc = fmaf(c1.w, w1.w, acc);
    acc = fmaf(c2.x, w2.x, acc); acc = fmaf(c2.y, w2.y, acc);
    acc = fmaf(c2.z, w2.z, acc); acc = fmaf(c2.w, w2.w, acc);
    acc = fmaf(c3.x, w3.x, acc); acc = fmaf(c3.y, w3.y, acc);
    acc = fmaf(c3.z, w3.z, acc); acc = fmaf(c3.w, w3.w, acc);
    return acc;
}

// ---------------- Phase 1: input projection ----------------
// 1 thread per (batch row, 8-timestep chunk, gate lane j).
// threads = 4096 * 64 * 4 = 1,048,576
__global__ __launch_bounds__(128, 1)
void gru_xproj(const float* __restrict__ x,
               const float* __restrict__ w_ih,
               const float* __restrict__ b_ih,
               const float* __restrict__ b_hh) {
    const int tid = blockIdx.x * 128 + threadIdx.x;
    const int j = tid & 3;
    const int chunk = tid >> 2;          // 262144 chunks
    const int b = chunk >> 6;            // 64 chunks per batch row
    const int t0 = (chunk & 63) << 3;    // 8 timesteps per chunk

    const float4* W = (const float4*)w_ih;   // rows of 16 floats = 4 float4
    const float4 wr0 = __ldg(&W[(j)     * 4 + 0]), wr1 = __ldg(&W[(j)     * 4 + 1]),
                 wr2 = __ldg(&W[(j)     * 4 + 2]), wr3 = __ldg(&W[(j)     * 4 + 3]);
    const float4 wz0 = __ldg(&W[(4 + j) * 4 + 0]), wz1 = __ldg(&W[(4 + j) * 4 + 1]),
                 wz2 = __ldg(&W[(4 + j) * 4 + 2]), wz3 = __ldg(&W[(4 + j) * 4 + 3]);
    const float4 wn0 = __ldg(&W[(8 + j) * 4 + 0]), wn1 = __ldg(&W[(8 + j) * 4 + 1]),
                 wn2 = __ldg(&W[(8 + j) * 4 + 2]), wn3 = __ldg(&W[(8 + j) * 4 + 3]);

    const float br = __ldg(&b_ih[j])     + __ldg(&b_hh[j]);      // fold b_hh (r)
    const float bz = __ldg(&b_ih[4 + j]) + __ldg(&b_hh[4 + j]);  // fold b_hh (z)
    const float bn = __ldg(&b_ih[8 + j]);                        // n: input side only

    const float4* xr = (const float4*)x + ((size_t)b * GT + t0) * 4;
    float4* op = g_xp + ((size_t)b * GT + t0) * 4 + j;

#pragma unroll
    for (int s = 0; s < 8; s++) {
        const float4 c0 = __ldcs(xr + s * 4 + 0);
        const float4 c1 = __ldcs(xr + s * 4 + 1);
        const float4 c2 = __ldcs(xr + s * 4 + 2);
        const float4 c3 = __ldcs(xr + s * 4 + 3);
        const float gr = dot16(c0, c1, c2, c3, wr0, wr1, wr2, wr3, br);
        const float gz = dot16(c0, c1, c2, c3, wz0, wz1, wz2, wz3, bz);
        const float gn = dot16(c0, c1, c2, c3, wn0, wn1, wn2, wn3, bn);
        op[s * 4] = make_float4(gr, gz, gn, 0.0f);
    }
}

// ---------------- Phase 2: recurrence scan ----------------
// 4 threads per batch row; thread j owns hidden component j and gate rows {j,4+j,8+j}.
__global__ __launch_bounds__(64, 1)
void gru_scan(const float* __restrict__ w_hh,
              const float* __restrict__ b_hh,
              const float* __restrict__ fc_w,
              const float* __restrict__ fc_b,
              float* __restrict__ out) {
    const int tid = blockIdx.x * 64 + threadIdx.x;
    const int b = tid >> 2;
    const int j = tid & 3;

    const float4* Wh = (const float4*)w_hh;   // rows of 4 floats = 1 float4
    const float4 whr = __ldg(&Wh[j]);
    const float4 whz = __ldg(&Wh[4 + j]);
    const float4 whn = __ldg(&Wh[8 + j]);
    const float bhn = __ldg(&b_hh[8 + j]);

    const float4* xp = g_xp + (size_t)b * GT * 4 + j;

    // 8-deep register prefetch ring
    float4 ring[8];
#pragma unroll
    for (int i = 0; i < 8; i++) ring[i] = __ldcs(xp + (size_t)i * 4);

    float h0 = 0.f, h1 = 0.f, h2 = 0.f, h3 = 0.f;

    for (int tb = 0; tb < GT; tb += 8) {
#pragma unroll
        for (int u = 0; u < 8; u++) {
            const float4 g = ring[u];
            int tn = tb + u + 8;
            if (tn > GT - 1) tn = GT - 1;   // clamped duplicate prefetch at the tail
            ring[u] = __ldcs(xp + (size_t)tn * 4);

            const float ghr = (h0 * whr.x + h1 * whr.y) + (h2 * whr.z + h3 * whr.w);
            const float ghz = (h0 * whz.x + h1 * whz.y) + (h2 * whz.z + h3 * whz.w);
            const float ghn = (h0 * whn.x + h1 * whn.y) + (h2 * whn.z + h3 * whn.w) + bhn;

            const float r = fast_sigmoid(g.x + ghr);
            const float z = fast_sigmoid(g.y + ghz);
            const float n = fast_tanh(fmaf(r, ghn, g.z));

            const float hj = (j == 0) ? h0 : (j == 1) ? h1 : (j == 2) ? h2 : h3;
            const float hn = fmaf(z, hj - n, n);

            h0 = __shfl_sync(0xffffffffu, hn, 0, 4);
            h1 = __shfl_sync(0xffffffffu, hn, 1, 4);
            h2 = __shfl_sync(0xffffffffu, hn, 2, 4);
            h3 = __shfl_sync(0xffffffffu, hn, 3, 4);
        }
    }

    if (j == 0) {
        const float fw0 = __ldg(&fc_w[0]), fw1 = __ldg(&fc_w[1]);
        const float fw2 = __ldg(&fc_w[2]), fw3 = __ldg(&fc_w[3]);
        out[b] = (h0 * fw0 + h1 * fw1) + (h2 * fw2 + h3 * fw3) + __ldg(&fc_b[0]);
    }
}

extern "C" void kernel_launch(void* const* d_in, const int* in_sizes, int n_in,
                              void* d_out, int out_size) {
    const float* x    = (const float*)d_in[0];
    const float* w_ih = (const float*)d_in[1];
    const float* w_hh = (const float*)d_in[2];
    const float* b_ih = (const float*)d_in[3];
    const float* b_hh = (const float*)d_in[4];
    const float* fc_w = (const float*)d_in[5];
    const float* fc_b = (const float*)d_in[6];
    float* out = (float*)d_out;

    // Phase 1: 1,048,576 threads / 128 = 8192 blocks
    gru_xproj<<<8192, 128>>>(x, w_ih, b_ih, b_hh);
    // Phase 2: 16384 threads / 64 = 256 blocks
    gru_scan<<<256, 64>>>(w_hh, b_hh, fc_w, fc_b, out);
}

// round 4
// speedup vs baseline: 2.9730x; 2.9730x over previous
#include <cuda_runtime.h>
#include <cstdint>

// UltraTinyGRU fused, smem-staged.
// B=4096, T=512, F=16, H=4. One block = 32 batch rows, 128 threads.
// 4 threads per row: thread j owns gate rows {j, 4+j, 8+j} and h component j.
// x streamed gmem->smem with cp.async double buffering (8 timesteps/stage):
// load completion is paid once per 8 steps, one full stage-compute after issue,
// so no DRAM latency appears on the recurrence chain.

#define GT 512
#define GF 16
#define ROWS 32           // batch rows per block
#define THREADS 128
#define SSTEPS 8          // timesteps per stage
#define NSTAGE_TOTAL (GT / SSTEPS)   // 64

__device__ __forceinline__ void cp_async16(void* smem_dst, const void* gmem_src) {
    unsigned int s = (unsigned int)__cvta_generic_to_shared(smem_dst);
    asm volatile("cp.async.cg.shared.global [%0], [%1], 16;\n"
                 :: "r"(s), "l"(gmem_src) : "memory");
}
__device__ __forceinline__ void cp_async_commit() {
    asm volatile("cp.async.commit_group;\n" ::: "memory");
}

__device__ __forceinline__ float fast_sigmoid(float x) {
    float e = __expf(-x);
    return __fdividef(1.0f, 1.0f + e);
}
__device__ __forceinline__ float fast_tanh(float x) {
    float e = __expf(-2.0f * x);
    return __fdividef(1.0f - e, 1.0f + e);
}

__device__ __forceinline__ float dot16(float4 c0, float4 c1, float4 c2, float4 c3,
                                       float4 w0, float4 w1, float4 w2, float4 w3,
                                       float acc) {
    acc = fmaf(c0.x, w0.x, acc); acc = fmaf(c0.y, w0.y, acc);
    acc = fmaf(c0.z, w0.z, acc); acc = fmaf(c0.w, w0.w, acc);
    acc = fmaf(c1.x, w1.x, acc); acc = fmaf(c1.y, w1.y, acc);
    acc = fmaf(c1.z, w1.z, acc); acc = fmaf(c1.w, w1.w, acc);
    acc = fmaf(c2.x, w2.x, acc); acc = fmaf(c2.y, w2.y, acc);
    acc = fmaf(c2.z, w2.z, acc); acc = fmaf(c2.w, w2.w, acc);
    acc = fmaf(c3.x, w3.x, acc); acc = fmaf(c3.y, w3.y, acc);
    acc = fmaf(c3.z, w3.z, acc); acc = fmaf(c3.w, w3.w, acc);
    return acc;
}

__global__ __launch_bounds__(THREADS, 1)
void gru_fused(const float* __restrict__ x,
               const float* __restrict__ w_ih,
               const float* __restrict__ w_hh,
               const float* __restrict__ b_ih,
               const float* __restrict__ b_hh,
               const float* __restrict__ fc_w,
               const float* __restrict__ fc_b,
               float* __restrict__ out) {
    // stage buffer: [2][row][33 float4]  (32 data float4 + 1 pad -> 528B row
    // stride, spreads rows across smem banks; quad reads are broadcast)
    __shared__ float4 sx[2][ROWS][33];

    const int tid = threadIdx.x;
    const int b0  = blockIdx.x * ROWS;
    const int row = tid >> 2;
    const int j   = tid & 3;
    const int b   = b0 + row;

    // ---- per-thread weights in registers ----
    const float4* W = (const float4*)w_ih;   // rows of 16 floats = 4 float4
    const float4 wr0 = __ldg(&W[(j)     * 4 + 0]), wr1 = __ldg(&W[(j)     * 4 + 1]),
                 wr2 = __ldg(&W[(j)     * 4 + 2]), wr3 = __ldg(&W[(j)     * 4 + 3]);
    const float4 wz0 = __ldg(&W[(4 + j) * 4 + 0]), wz1 = __ldg(&W[(4 + j) * 4 + 1]),
                 wz2 = __ldg(&W[(4 + j) * 4 + 2]), wz3 = __ldg(&W[(4 + j) * 4 + 3]);
    const float4 wn0 = __ldg(&W[(8 + j) * 4 + 0]), wn1 = __ldg(&W[(8 + j) * 4 + 1]),
                 wn2 = __ldg(&W[(8 + j) * 4 + 2]), wn3 = __ldg(&W[(8 + j) * 4 + 3]);

    const float4* Wh = (const float4*)w_hh;  // rows of 4 floats
    const float4 whr = __ldg(&Wh[j]);
    const float4 whz = __ldg(&Wh[4 + j]);
    const float4 whn = __ldg(&Wh[8 + j]);

    const float br  = __ldg(&b_ih[j])     + __ldg(&b_hh[j]);
    const float bz  = __ldg(&b_ih[4 + j]) + __ldg(&b_hh[4 + j]);
    const float bin = __ldg(&b_ih[8 + j]);
    const float bhn = __ldg(&b_hh[8 + j]);

    // ---- stage copy helper: 128 threads move 32 rows x 512B ----
    // copy index c = 0..1023 : row = c>>5, chunk = c&31 (16B each)
    const float4* xbase = (const float4*)x;  // x[b][t][f] -> float4 index (b*512+t)*4 + q
    auto issue_stage = [&](int s, int buf) {
#pragma unroll
        for (int it = 0; it < 8; it++) {
            const int c     = tid + it * THREADS;
            const int crow  = c >> 5;
            const int chunk = c & 31;
            const float4* src = xbase + ((size_t)(b0 + crow) * GT + s * SSTEPS) * 4 + chunk;
            cp_async16(&sx[buf][crow][chunk], src);
        }
        cp_async_commit();
    };

    issue_stage(0, 0);
    issue_stage(1, 1);

    float h0 = 0.f, h1 = 0.f, h2 = 0.f, h3 = 0.f;

    for (int s = 0; s < NSTAGE_TOTAL; s++) {
        if (s == NSTAGE_TOTAL - 1) {
            asm volatile("cp.async.wait_group 0;\n" ::: "memory");
        } else {
            asm volatile("cp.async.wait_group 1;\n" ::: "memory");
        }
        __syncthreads();

        const float4* rx = &sx[s & 1][row][0];
#pragma unroll
        for (int u = 0; u < SSTEPS; u++) {
            const float4 c0 = rx[u * 4 + 0];
            const float4 c1 = rx[u * 4 + 1];
            const float4 c2 = rx[u * 4 + 2];
            const float4 c3 = rx[u * 4 + 3];

            // input-side gate dots: off the recurrence chain
            const float gr = dot16(c0, c1, c2, c3, wr0, wr1, wr2, wr3, br);
            const float gz = dot16(c0, c1, c2, c3, wz0, wz1, wz2, wz3, bz);
            const float gn = dot16(c0, c1, c2, c3, wn0, wn1, wn2, wn3, bin);

            // hidden-side dots (tree-shaped)
            const float ghr = (h0 * whr.x + h1 * whr.y) + (h2 * whr.z + h3 * whr.w);
            const float ghz = (h0 * whz.x + h1 * whz.y) + (h2 * whz.z + h3 * whz.w);
            const float ghn = (h0 * whn.x + h1 * whn.y) + (h2 * whn.z + h3 * whn.w) + bhn;

            const float r = fast_sigmoid(gr + ghr);
            const float z = fast_sigmoid(gz + ghz);
            const float n = fast_tanh(fmaf(r, ghn, gn));

            const float hj = (j == 0) ? h0 : (j == 1) ? h1 : (j == 2) ? h2 : h3;
            const float hn = fmaf(z, hj - n, n);

            h0 = __shfl_sync(0xffffffffu, hn, 0, 4);
            h1 = __shfl_sync(0xffffffffu, hn, 1, 4);
            h2 = __shfl_sync(0xffffffffu, hn, 2, 4);
            h3 = __shfl_sync(0xffffffffu, hn, 3, 4);
        }
        __syncthreads();   // everyone done reading buf (s&1) before refill

        if (s < NSTAGE_TOTAL - 2) {
            issue_stage(s + 2, s & 1);
        }
    }

    if (j == 0) {
        const float fw0 = __ldg(&fc_w[0]), fw1 = __ldg(&fc_w[1]);
        const float fw2 = __ldg(&fc_w[2]), fw3 = __ldg(&fc_w[3]);
        out[b] = (h0 * fw0 + h1 * fw1) + (h2 * fw2 + h3 * fw3) + __ldg(&fc_b[0]);
    }
}

extern "C" void kernel_launch(void* const* d_in, const int* in_sizes, int n_in,
                              void* d_out, int out_size) {
    const float* x    = (const float*)d_in[0];
    const float* w_ih = (const float*)d_in[1];
    const float* w_hh = (const float*)d_in[2];
    const float* b_ih = (const float*)d_in[3];
    const float* b_hh = (const float*)d_in[4];
    const float* fc_w = (const float*)d_in[5];
    const float* fc_b = (const float*)d_in[6];
    float* out = (float*)d_out;

    const int B = out_size;                    // 4096
    const int blocks = B / ROWS;               // 128 blocks, <=1 per SM

    gru_fused<<<blocks, THREADS>>>(x, w_ih, w_hh, b_ih, b_hh, fc_w, fc_b, out);
}

// round 6
// speedup vs baseline: 6.1388x; 2.0648x over previous
#include <cuda_runtime.h>
#include <cstdint>

// UltraTinyGRU fused, smem-staged, MUFU.TANH activations, f32x2 input dots.
// B=4096, T=512, F=16, H=4. Block = 32 batch rows, 128 threads.
// Thread j of each quad owns gate rows {j, 4+j, 8+j} and h component j.
// sigmoid(v) = 0.5 + 0.5*tanh(v/2): the 1/2 is folded into the r/z weights
// and biases (and the hidden-side n weights), so the chain sees only
// FMA -> MUFU.TANH -> FMA sequences.

#define GT 512
#define ROWS 32
#define THREADS 128
#define SSTEPS 8
#define NSTAGE (GT / SSTEPS)

__device__ __forceinline__ void cp_async16(void* smem_dst, const void* gmem_src) {
    unsigned int s = (unsigned int)__cvta_generic_to_shared(smem_dst);
    asm volatile("cp.async.cg.shared.global [%0], [%1], 16;\n"
                 :: "r"(s), "l"(gmem_src) : "memory");
}
__device__ __forceinline__ void cp_async_commit() {
    asm volatile("cp.async.commit_group;\n" ::: "memory");
}

__device__ __forceinline__ float tanh_fast(float x) {
    float y;
    asm("tanh.approx.f32 %0, %1;" : "=f"(y) : "f"(x));
    return y;
}

// ---- packed fp32x2 helpers (Blackwell FFMA2 path) ----
__device__ __forceinline__ double pack2(float lo, float hi) {
    double d;
    asm("mov.b64 %0, {%1, %2};" : "=d"(d) : "f"(lo), "f"(hi));
    return d;
}
__device__ __forceinline__ double fma2(double a, double b, double c) {
    double d;
    asm("fma.rn.f32x2 %0, %1, %2, %3;" : "=d"(d) : "d"(a), "d"(b), "d"(c));
    return d;
}
__device__ __forceinline__ double mul2(double a, double b) {
    double d;
    asm("mul.rn.f32x2 %0, %1, %2;" : "=d"(d) : "d"(a), "d"(b));
    return d;
}
__device__ __forceinline__ double add2(double a, double b) {
    double d;
    asm("add.rn.f32x2 %0, %1, %2;" : "=d"(d) : "d"(a), "d"(b));
    return d;
}
__device__ __forceinline__ float2 unpack2(double d) {
    float2 r;
    asm("mov.b64 {%0, %1}, %2;" : "=f"(r.x), "=f"(r.y) : "d"(d));
    return r;
}

// pack a (possibly scaled) float4 row chunk into two f32x2 pairs
__device__ __forceinline__ void pack_row(float4 v, float scale, double* dst) {
    dst[0] = pack2(v.x * scale, v.y * scale);
    dst[1] = pack2(v.z * scale, v.w * scale);
}

__global__ __launch_bounds__(THREADS, 1)
void gru_fused(const float* __restrict__ x,
               const float* __restrict__ w_ih,
               const float* __restrict__ w_hh,
               const float* __restrict__ b_ih,
               const float* __restrict__ b_hh,
               const float* __restrict__ fc_w,
               const float* __restrict__ fc_b,
               float* __restrict__ out) {
    // [2 stages][row][33 float4] -> 528B row stride (16B-aligned, bank-spread)
    __shared__ float4 sx[2][ROWS][33];

    const int tid = threadIdx.x;
    const int b0  = blockIdx.x * ROWS;
    const int row = tid >> 2;
    const int j   = tid & 3;
    const int b   = b0 + row;

    // ---- pack input-side weights; r/z rows pre-halved ----
    const float4* W = (const float4*)w_ih;   // 16 floats/row = 4 float4
    double wrP[8], wzP[8], wnP[8];
#pragma unroll
    for (int q = 0; q < 4; q++) {
        pack_row(__ldg(&W[(j)     * 4 + q]), 0.5f, &wrP[q * 2]);
        pack_row(__ldg(&W[(4 + j) * 4 + q]), 0.5f, &wzP[q * 2]);
        pack_row(__ldg(&W[(8 + j) * 4 + q]), 1.0f, &wnP[q * 2]);
    }

    // hidden-side weights: r/z and n all pre-halved
    const float4* Wh = (const float4*)w_hh;
    float4 whr = __ldg(&Wh[j]);
    float4 whz = __ldg(&Wh[4 + j]);
    float4 whn = __ldg(&Wh[8 + j]);
    whr.x *= 0.5f; whr.y *= 0.5f; whr.z *= 0.5f; whr.w *= 0.5f;
    whz.x *= 0.5f; whz.y *= 0.5f; whz.z *= 0.5f; whz.w *= 0.5f;
    whn.x *= 0.5f; whn.y *= 0.5f; whn.z *= 0.5f; whn.w *= 0.5f;

    const float brh  = 0.5f * (__ldg(&b_ih[j])     + __ldg(&b_hh[j]));
    const float bzh  = 0.5f * (__ldg(&b_ih[4 + j]) + __ldg(&b_hh[4 + j]));
    const float bin  = __ldg(&b_ih[8 + j]);
    const float bhnh = 0.5f * __ldg(&b_hh[8 + j]);

    const double biasR = pack2(brh, 0.0f);
    const double biasZ = pack2(bzh, 0.0f);
    const double biasN = pack2(bin, 0.0f);

    // ---- stage copy: 128 threads move 32 rows x 512B ----
    const float4* xbase = (const float4*)x;
    auto issue_stage = [&](int s, int buf) {
#pragma unroll
        for (int it = 0; it < 8; it++) {
            const int c     = tid + it * THREADS;
            const int crow  = c >> 5;
            const int chunk = c & 31;
            const float4* src = xbase + ((size_t)(b0 + crow) * GT + s * SSTEPS) * 4 + chunk;
            cp_async16(&sx[buf][crow][chunk], src);
        }
        cp_async_commit();
    };

    issue_stage(0, 0);
    issue_stage(1, 1);

    float h0 = 0.f, h1 = 0.f, h2 = 0.f, h3 = 0.f;
    float hhalf = 0.f;   // 0.5 * own h component

    for (int s = 0; s < NSTAGE; s++) {
        if (s == NSTAGE - 1) {
            asm volatile("cp.async.wait_group 0;\n" ::: "memory");
        } else {
            asm volatile("cp.async.wait_group 1;\n" ::: "memory");
        }
        __syncthreads();

        const double2* rx2 = (const double2*)&sx[s & 1][row][0];
#pragma unroll
        for (int u = 0; u < SSTEPS; u++) {
            const double2 q0 = rx2[u * 4 + 0];
            const double2 q1 = rx2[u * 4 + 1];
            const double2 q2 = rx2[u * 4 + 2];
            const double2 q3 = rx2[u * 4 + 3];

            // packed input-side dots (off the recurrence chain)
            double aR = fma2(q0.x, wrP[0], biasR);
            aR = fma2(q0.y, wrP[1], aR);
            aR = fma2(q1.x, wrP[2], aR);
            aR = fma2(q1.y, wrP[3], aR);
            double bR = mul2(q2.x, wrP[4]);
            bR = fma2(q2.y, wrP[5], bR);
            bR = fma2(q3.x, wrP[6], bR);
            bR = fma2(q3.y, wrP[7], bR);
            const float2 uR = unpack2(add2(aR, bR));
            const float grh = uR.x + uR.y;

            double aZ = fma2(q0.x, wzP[0], biasZ);
            aZ = fma2(q0.y, wzP[1], aZ);
            aZ = fma2(q1.x, wzP[2], aZ);
            aZ = fma2(q1.y, wzP[3], aZ);
            double bZ = mul2(q2.x, wzP[4]);
            bZ = fma2(q2.y, wzP[5], bZ);
            bZ = fma2(q3.x, wzP[6], bZ);
            bZ = fma2(q3.y, wzP[7], bZ);
            const float2 uZ = unpack2(add2(aZ, bZ));
            const float gzh = uZ.x + uZ.y;

            double aN = fma2(q0.x, wnP[0], biasN);
            aN = fma2(q0.y, wnP[1], aN);
            aN = fma2(q1.x, wnP[2], aN);
            aN = fma2(q1.y, wnP[3], aN);
            double bN = mul2(q2.x, wnP[4]);
            bN = fma2(q2.y, wnP[5], bN);
            bN = fma2(q3.x, wnP[6], bN);
            bN = fma2(q3.y, wnP[7], bN);
            const float2 uN = unpack2(add2(aN, bN));
            const float gnf = uN.x + uN.y;

            // ---- recurrence chain ----
            float ar = fmaf(h0, whr.x, grh); ar = fmaf(h1, whr.y, ar);
            float cr = h2 * whr.z;           cr = fmaf(h3, whr.w, cr);
            const float arg_r = ar + cr;

            float az = fmaf(h0, whz.x, gzh); az = fmaf(h1, whz.y, az);
            float cz = h2 * whz.z;           cz = fmaf(h3, whz.w, cz);
            const float arg_z = az + cz;

            float an = fmaf(h0, whn.x, bhnh); an = fmaf(h1, whn.y, an);
            float cn = h2 * whn.z;            cn = fmaf(h3, whn.w, cn);
            const float ghn_h = an + cn;      // 0.5 * (h.w_hh_n + b_hh_n)

            const float tr = tanh_fast(arg_r);       // r = 0.5 + 0.5*tr
            const float tz = tanh_fast(arg_z);       // z = 0.5 + 0.5*tz

            const float gnp  = gnf + ghn_h;          // gn + 0.5*ghn
            const float narg = fmaf(tr, ghn_h, gnp); // gn + r*ghn
            const float n    = tanh_fast(narg);

            // hn = (1-z)*n + z*h = n + (0.5+0.5tz)*(h-n)
            const float dd = fmaf(n, -0.5f, hhalf);  // 0.5*(h_own - n)
            const float nt = n + dd;
            const float hn = fmaf(tz, dd, nt);

            hhalf = 0.5f * hn;
            h0 = __shfl_sync(0xffffffffu, hn, 0, 4);
            h1 = __shfl_sync(0xffffffffu, hn, 1, 4);
            h2 = __shfl_sync(0xffffffffu, hn, 2, 4);
            h3 = __shfl_sync(0xffffffffu, hn, 3, 4);
        }
        __syncthreads();

        if (s < NSTAGE - 2) {
            issue_stage(s + 2, s & 1);
        }
    }

    if (j == 0) {
        const float fw0 = __ldg(&fc_w[0]), fw1 = __ldg(&fc_w[1]);
        const float fw2 = __ldg(&fc_w[2]), fw3 = __ldg(&fc_w[3]);
        out[b] = (h0 * fw0 + h1 * fw1) + (h2 * fw2 + h3 * fw3) + __ldg(&fc_b[0]);
    }
}

extern "C" void kernel_launch(void* const* d_in, const int* in_sizes, int n_in,
                              void* d_out, int out_size) {
    const float* x    = (const float*)d_in[0];
    const float* w_ih = (const float*)d_in[1];
    const float* w_hh = (const float*)d_in[2];
    const float* b_ih = (const float*)d_in[3];
    const float* b_hh = (const float*)d_in[4];
    const float* fc_w = (const float*)d_in[5];
    const float* fc_b = (const float*)d_in[6];
    float* out = (float*)d_out;

    const int B = out_size;          // 4096
    const int blocks = B / ROWS;     // 128

    gru_fused<<<blocks, THREADS>>>(x, w_ih, w_hh, b_ih, b_hh, fc_w, fc_b, out);
}